// round 14
// baseline (speedup 1.0000x reference)
#include <cuda_runtime.h>
#include <math.h>

#define EPSV 1e-4f
#define NB   16
#define HP   14
#define NP   196
#define TP   3136
#define PTMAX 11
#define NBLK 296          // = 2 * 148 SMs: single wave at occ 2
#define PROTO 60

__device__ __forceinline__ float fsqrt_approx(float x) {
    float r; asm("sqrt.approx.f32 %0, %1;" : "=f"(r) : "f"(x)); return r;
}
__device__ __forceinline__ float act_fn(float d) {
    return __logf((d + 1.0f) / (d + EPSV));
}

// scratch (allocation-free: device globals)
__device__ float g_dist[NB*PROTO*NP];
__device__ float g_act [NB*PROTO*NP];

// transposed + k-pair-interleaved weights: g_Wt2[k2*O + o] = {W[o][2k2], W[o][2k2+1]}
__device__ float2 g_Wft2[384*512];
__device__ float2 g_W1t2[256*256];
__device__ float2 g_W2t2[128*256];
__device__ float2 g_W3t2[128*128];
__device__ float2 g_W4t2[ 64*128];

// ---------------------------------------------------------------------------
// K0: tiled transpose into paired [k2][o] float2 layout (proven).
// ---------------------------------------------------------------------------
__global__ __launch_bounds__(256) void k_tr(
    const float* __restrict__ Wf, const float* __restrict__ W1,
    const float* __restrict__ W2, const float* __restrict__ W3,
    const float* __restrict__ W4)
{
    __shared__ float tile[32][33];
    int bid = blockIdx.x;
    const float* src; float2* dst; int O, K, ot, kt;
    if (bid < 384)      { src=Wf; dst=g_Wft2; O=512; K=768; int r=bid;     ot=r/24; kt=r%24; }
    else if (bid < 512) { src=W1; dst=g_W1t2; O=256; K=512; int r=bid-384; ot=r/16; kt=r%16; }
    else if (bid < 576) { src=W2; dst=g_W2t2; O=256; K=256; int r=bid-512; ot=r/8;  kt=r%8;  }
    else if (bid < 608) { src=W3; dst=g_W3t2; O=128; K=256; int r=bid-576; ot=r/8;  kt=r%8;  }
    else                { src=W4; dst=g_W4t2; O=128; K=128; int r=bid-608; ot=r/4;  kt=r%4;  }
    int o0 = ot*32, k0 = kt*32;

    int tx = threadIdx.x & 31;
    int ty = threadIdx.x >> 5;
    #pragma unroll
    for (int s = 0; s < 4; s++) {
        int oy = ty + s*8;
        tile[tx][oy] = src[(size_t)(o0+oy)*K + k0 + tx];
    }
    __syncthreads();

    int oL  = threadIdx.x & 31;
    int k2b = threadIdx.x >> 5;
    #pragma unroll
    for (int s = 0; s < 2; s++) {
        int k2L = k2b + s*8;     // 0..15
        dst[(size_t)(k0/2 + k2L)*O + o0 + oL] =
            make_float2(tile[2*k2L][oL], tile[2*k2L+1][oL]);
    }
}

// ---------------------------------------------------------------------------
// K1 body: fused patch-conv + MLP + distances. Proven loop structure,
// templated on patch count (PTN=11 and PTN=10). Stages 3/4 compute all 6
// lanes unguarded (in-bounds garbage for pt>=PTN) and guard only the stores.
// ---------------------------------------------------------------------------
template<int PTN>
__device__ __forceinline__ void mlp_body(
    int gp0, int tid, float* sA, float* sB, float* sC,
    const float* __restrict__ x,
    const float* __restrict__ bf, const float* __restrict__ b1,
    const float* __restrict__ b2, const float* __restrict__ b3,
    const float* __restrict__ b4, const float* __restrict__ prot)
{
    // ---- load PTN patches of input (3x16x16 each) into sA
    for (int e = tid; e < PTN*768; e += 256) {
        int pt = e / 768, k = e - pt*768;
        int c = k >> 8, r = (k >> 4) & 15, col = k & 15;
        int gp = gp0 + pt;
        int b = gp / NP, hw = gp - b*NP;
        int py = hw / HP, px = hw - py*HP;
        sA[e] = x[((b*3 + c)*224 + py*16 + r)*224 + px*16 + col];
    }
    __syncthreads();

    // ---- stage 0: 512 outputs (2/thread), K=768 : sA -> sB
    {
        float acc0[PTN], acc1[PTN];
        #pragma unroll
        for (int pt = 0; pt < PTN; pt++) { acc0[pt] = 0.f; acc1[pt] = 0.f; }
        #pragma unroll 2
        for (int k = 0; k < 768; k += 4) {
            float2 wa0 = g_Wft2[(k>>1)*512 + tid];
            float2 wa1 = g_Wft2[((k>>1)+1)*512 + tid];
            float2 wb0 = g_Wft2[(k>>1)*512 + tid + 256];
            float2 wb1 = g_Wft2[((k>>1)+1)*512 + tid + 256];
            #pragma unroll
            for (int pt = 0; pt < PTN; pt++) {
                float4 a = *(const float4*)&sA[pt*768 + k];
                acc0[pt] = fmaf(wa0.x, a.x, acc0[pt]);
                acc0[pt] = fmaf(wa0.y, a.y, acc0[pt]);
                acc0[pt] = fmaf(wa1.x, a.z, acc0[pt]);
                acc0[pt] = fmaf(wa1.y, a.w, acc0[pt]);
                acc1[pt] = fmaf(wb0.x, a.x, acc1[pt]);
                acc1[pt] = fmaf(wb0.y, a.y, acc1[pt]);
                acc1[pt] = fmaf(wb1.x, a.z, acc1[pt]);
                acc1[pt] = fmaf(wb1.y, a.w, acc1[pt]);
            }
        }
        float bb0 = bf[tid], bb1 = bf[tid + 256];
        #pragma unroll
        for (int pt = 0; pt < PTN; pt++) {
            sB[pt*512 + tid]       = fmaxf(acc0[pt] + bb0, 0.f);
            sB[pt*512 + tid + 256] = fmaxf(acc1[pt] + bb1, 0.f);
        }
    }
    __syncthreads();

    // ---- stage 1: 256 outputs, K=512 : sB -> sC
    {
        float acc[PTN];
        #pragma unroll
        for (int pt = 0; pt < PTN; pt++) acc[pt] = 0.f;
        #pragma unroll 2
        for (int k = 0; k < 512; k += 4) {
            float2 w0 = g_W1t2[(k>>1)*256 + tid];
            float2 w1 = g_W1t2[((k>>1)+1)*256 + tid];
            #pragma unroll
            for (int pt = 0; pt < PTN; pt++) {
                float4 a = *(const float4*)&sB[pt*512 + k];
                acc[pt] = fmaf(w0.x, a.x, acc[pt]);
                acc[pt] = fmaf(w0.y, a.y, acc[pt]);
                acc[pt] = fmaf(w1.x, a.z, acc[pt]);
                acc[pt] = fmaf(w1.y, a.w, acc[pt]);
            }
        }
        float bb = b1[tid];
        #pragma unroll
        for (int pt = 0; pt < PTN; pt++)
            sC[pt*256 + tid] = fmaxf(acc[pt] + bb, 0.f);
    }
    __syncthreads();

    // ---- stage 2: 256 outputs, K=256 : sC -> sA (reuse)
    {
        float acc[PTN];
        #pragma unroll
        for (int pt = 0; pt < PTN; pt++) acc[pt] = 0.f;
        #pragma unroll 2
        for (int k = 0; k < 256; k += 4) {
            float2 w0 = g_W2t2[(k>>1)*256 + tid];
            float2 w1 = g_W2t2[((k>>1)+1)*256 + tid];
            #pragma unroll
            for (int pt = 0; pt < PTN; pt++) {
                float4 a = *(const float4*)&sC[pt*256 + k];
                acc[pt] = fmaf(w0.x, a.x, acc[pt]);
                acc[pt] = fmaf(w0.y, a.y, acc[pt]);
                acc[pt] = fmaf(w1.x, a.z, acc[pt]);
                acc[pt] = fmaf(w1.y, a.w, acc[pt]);
            }
        }
        float bb = b2[tid];
        #pragma unroll
        for (int pt = 0; pt < PTN; pt++)
            sA[pt*256 + tid] = fmaxf(acc[pt] + bb, 0.f);
    }
    __syncthreads();

    // ---- stage 3: 128 outputs, K=256 : sA -> sB (thread: 1 out x 6 patches,
    //      unguarded compute, guarded store)
    {
        const int o = tid & 127;
        const int half = tid >> 7;
        float acc[6] = {0.f, 0.f, 0.f, 0.f, 0.f, 0.f};
        #pragma unroll 2
        for (int k = 0; k < 256; k += 4) {
            float2 w0 = g_W3t2[(k>>1)*128 + o];
            float2 w1 = g_W3t2[((k>>1)+1)*128 + o];
            #pragma unroll
            for (int j = 0; j < 6; j++) {
                float4 a = *(const float4*)&sA[(half*6 + j)*256 + k];
                acc[j] = fmaf(w0.x, a.x, acc[j]);
                acc[j] = fmaf(w0.y, a.y, acc[j]);
                acc[j] = fmaf(w1.x, a.z, acc[j]);
                acc[j] = fmaf(w1.y, a.w, acc[j]);
            }
        }
        float bb = b3[o];
        #pragma unroll
        for (int j = 0; j < 6; j++) {
            int pt = half*6 + j;
            if (pt < PTN)
                sB[pt*128 + o] = fmaxf(acc[j] + bb, 0.f);
        }
    }
    __syncthreads();

    // ---- stage 4: 128 outputs, K=128, sigmoid : sB -> sC
    {
        const int o = tid & 127;
        const int half = tid >> 7;
        float acc[6] = {0.f, 0.f, 0.f, 0.f, 0.f, 0.f};
        #pragma unroll 2
        for (int k = 0; k < 128; k += 4) {
            float2 w0 = g_W4t2[(k>>1)*128 + o];
            float2 w1 = g_W4t2[((k>>1)+1)*128 + o];
            #pragma unroll
            for (int j = 0; j < 6; j++) {
                float4 a = *(const float4*)&sB[(half*6 + j)*128 + k];
                acc[j] = fmaf(w0.x, a.x, acc[j]);
                acc[j] = fmaf(w0.y, a.y, acc[j]);
                acc[j] = fmaf(w1.x, a.z, acc[j]);
                acc[j] = fmaf(w1.y, a.w, acc[j]);
            }
        }
        float bb = b4[o];
        #pragma unroll
        for (int j = 0; j < 6; j++) {
            int pt = half*6 + j;
            if (pt < PTN) {
                float z = acc[j] + bb;
                sC[pt*128 + o] = __fdividef(1.0f, 1.0f + __expf(-z));
            }
        }
    }
    __syncthreads();

    // ---- prototype distances + activation: 60 protos x PTN patches
    for (int q = tid; q < PROTO*PTN; q += 256) {
        int p = q / PTN, pt = q - p*PTN;
        const float* pr = prot + p*128;
        const float* hh = sC + pt*128;
        float acc = 0.f;
        #pragma unroll 8
        for (int k = 0; k < 128; k += 4) {
            float4 h4 = *(const float4*)&hh[k];
            float4 p4 = *(const float4*)&pr[k];
            float d0 = h4.x - p4.x, d1 = h4.y - p4.y;
            float d2 = h4.z - p4.z, d3 = h4.w - p4.w;
            acc = fmaf(d0, d0, acc); acc = fmaf(d1, d1, acc);
            acc = fmaf(d2, d2, acc); acc = fmaf(d3, d3, acc);
        }
        float d = fsqrt_approx(acc);
        float a = act_fn(d);
        int gp = gp0 + pt;
        int b = gp / NP, hw = gp - b*NP;
        int idx = (b*PROTO + p)*NP + hw;
        g_dist[idx] = d;
        g_act[idx]  = a;
    }
}

__global__ __launch_bounds__(256, 2) void k_mlp(
    const float* __restrict__ x,
    const float* __restrict__ bf, const float* __restrict__ b1,
    const float* __restrict__ b2, const float* __restrict__ b3,
    const float* __restrict__ b4, const float* __restrict__ prot)
{
    extern __shared__ float sm[];
    float* sA = sm;                 // PTMAX*768; reused as h2
    float* sB = sm + PTMAX*768;     // PTMAX*512; reused as h3
    float* sC = sB + PTMAX*512;     // PTMAX*256; h1, then h4

    const int tid = threadIdx.x;
    const int bid = blockIdx.x;

    // 176 blocks of 11 patches + 120 blocks of 10 patches = 3136
    if (bid < 176) {
        mlp_body<11>(bid*11, tid, sA, sB, sC, x, bf, b1, b2, b3, b4, prot);
    } else {
        mlp_body<10>(1936 + (bid-176)*10, tid, sA, sB, sC, x, bf, b1, b2, b3, b4, prot);
    }
}

// ---------------------------------------------------------------------------
// K2: per-batch top-k + logits (proven). One block per image, 16 warps.
// ---------------------------------------------------------------------------
__global__ __launch_bounds__(512) void k_tkl(
    const int* __restrict__ kptr, const float* __restrict__ lastW,
    float* __restrict__ out_log, float* __restrict__ out_mind)
{
    __shared__ float sp[PROTO];
    const int b    = blockIdx.x;
    const int warp = threadIdx.x >> 5;
    const int lane = threadIdx.x & 31;
    const int k    = *kptr;

    for (int p = warp; p < PROTO; p += 16) {
        const float* dp = g_dist + (b*PROTO + p)*NP;
        float v[7];
        #pragma unroll
        for (int j = 0; j < 7; j++) {
            int i = lane + 32*j;
            v[j] = (i < NP) ? dp[i] : 1e30f;
        }
        float sd = 0.f, sa = 0.f;
        for (int it = 0; it < k; it++) {
            float m = v[0]; int mj = 0;
            #pragma unroll
            for (int j = 1; j < 7; j++) if (v[j] < m) { m = v[j]; mj = j; }
            float bm = m; int bidx = (mj << 5) | lane;
            #pragma unroll
            for (int off = 16; off; off >>= 1) {
                float om = __shfl_xor_sync(0xffffffffu, bm, off);
                int   oi = __shfl_xor_sync(0xffffffffu, bidx, off);
                if (om < bm || (om == bm && oi < bidx)) { bm = om; bidx = oi; }
            }
            sd += bm;
            sa += act_fn(bm);
            if (lane == (bidx & 31)) v[bidx >> 5] = 1e30f;
        }
        if (lane == 0) {
            out_mind[b*PROTO + p] = sd / (float)k;
            sp[p] = sa / (float)k;
        }
    }
    __syncthreads();
    int t = threadIdx.x;
    if (t < 3) {
        float s = 0.f;
        #pragma unroll
        for (int p = 0; p < PROTO; p++)
            s += sp[p] * lastW[t*PROTO + p];
        out_log[b*3 + t] = s;
    }
}

// ---------------------------------------------------------------------------
// K3: 16x upsample. 2 feature-rows per block, one contiguous 28672B
// cp.async.bulk store. At the LTS ceiling (~6.4 TB/s effective) — frozen.
// ---------------------------------------------------------------------------
__global__ __launch_bounds__(128) void k_ups(float* __restrict__ out_up)
{
    __shared__ alignas(128) float buf[7168];   // 32 rows x 224 = 28672 B
    __shared__ float sv[28];
    const int bid = blockIdx.x;                // 16*60*7 = 6720
    const int bp  = bid / 7;
    const int py0 = (bid - bp*7) * 2;
    const int tid = threadIdx.x;

    if (tid < 28) sv[tid] = g_act[bp*NP + py0*HP + tid];  // 2 rows of 14
    __syncthreads();

    #pragma unroll
    for (int it = 0; it < 14; it++) {
        int idx = tid + it*128;        // float4 index 0..1791
        int row = idx / 56;            // 0..31 output rows
        int xq  = idx - row*56;
        float v = sv[(row >> 4)*14 + (xq >> 2)];
        ((float4*)buf)[idx] = make_float4(v, v, v, v);
    }
    __syncthreads();

    if (tid == 0) {
        float* dst = out_up + (size_t)bp*50176 + (size_t)py0*3584;
        unsigned saddr = (unsigned)__cvta_generic_to_shared(buf);
        asm volatile("fence.proxy.async.shared::cta;" ::: "memory");
        asm volatile("cp.async.bulk.global.shared::cta.bulk_group [%0], [%1], %2;"
                     :: "l"(dst), "r"(saddr), "r"(28672) : "memory");
        asm volatile("cp.async.bulk.commit_group;" ::: "memory");
        asm volatile("cp.async.bulk.wait_group 0;" ::: "memory");
    }
}

// ---------------------------------------------------------------------------
extern "C" void kernel_launch(void* const* d_in, const int* in_sizes, int n_in,
                              void* d_out, int out_size)
{
    const float* x    = (const float*)d_in[0];
    // d_in[1] = mascaras (unused by reference)
    const float* Wf   = (const float*)d_in[2];
    const float* bf   = (const float*)d_in[3];
    const float* W1   = (const float*)d_in[4];
    const float* b1   = (const float*)d_in[5];
    const float* W2   = (const float*)d_in[6];
    const float* b2   = (const float*)d_in[7];
    const float* W3   = (const float*)d_in[8];
    const float* b3   = (const float*)d_in[9];
    const float* W4   = (const float*)d_in[10];
    const float* b4   = (const float*)d_in[11];
    const float* prot = (const float*)d_in[12];
    const float* lastW= (const float*)d_in[13];
    const int*   kptr = (const int*)d_in[14];
    float* out = (float*)d_out;

    const int SMEM = (PTMAX*768 + PTMAX*512 + PTMAX*256) * 4;   // 67584 bytes
    cudaFuncSetAttribute(k_mlp, cudaFuncAttributeMaxDynamicSharedMemorySize, SMEM);

    // output packing: logits[48] | min_distances[960] | upsampled[16*60*224*224]
    k_tr <<<624, 256>>>(Wf, W1, W2, W3, W4);
    k_mlp<<<NBLK, 256, SMEM>>>(x, bf, b1, b2, b3, b4, prot);
    k_tkl<<<NB, 512>>>(kptr, lastW, out, out + 48);
    k_ups<<<6720, 128>>>(out + 48 + NB*PROTO);
}

// round 15
// speedup vs baseline: 1.0392x; 1.0392x over previous
#include <cuda_runtime.h>
#include <math.h>

#define EPSV 1e-4f
#define NB   16
#define HP   14
#define NP   196
#define TP   3136
#define PTMAX 11
#define NBLK 296          // = 2 * 148 SMs: single wave at occ 2
#define PROTO 60

// scratch (allocation-free: device globals)
__device__ float g_dist[NB*PROTO*NP];
__device__ float g_act [NB*PROTO*NP];

// transposed + k-pair-interleaved weights: g_Wt2[k2*O + o] = {W[o][2k2], W[o][2k2+1]}
__device__ float2 g_Wft2[384*512];
__device__ float2 g_W1t2[256*256];
__device__ float2 g_W2t2[128*256];
__device__ float2 g_W3t2[128*128];
__device__ float2 g_W4t2[ 64*128];

// ---------------------------------------------------------------------------
// K0: tiled transpose into paired [k2][o] float2 layout (proven).
// ---------------------------------------------------------------------------
__global__ __launch_bounds__(256) void k_tr(
    const float* __restrict__ Wf, const float* __restrict__ W1,
    const float* __restrict__ W2, const float* __restrict__ W3,
    const float* __restrict__ W4)
{
    __shared__ float tile[32][33];
    int bid = blockIdx.x;
    const float* src; float2* dst; int O, K, ot, kt;
    if (bid < 384)      { src=Wf; dst=g_Wft2; O=512; K=768; int r=bid;     ot=r/24; kt=r%24; }
    else if (bid < 512) { src=W1; dst=g_W1t2; O=256; K=512; int r=bid-384; ot=r/16; kt=r%16; }
    else if (bid < 576) { src=W2; dst=g_W2t2; O=256; K=256; int r=bid-512; ot=r/8;  kt=r%8;  }
    else if (bid < 608) { src=W3; dst=g_W3t2; O=128; K=256; int r=bid-576; ot=r/8;  kt=r%8;  }
    else                { src=W4; dst=g_W4t2; O=128; K=128; int r=bid-608; ot=r/4;  kt=r%4;  }
    int o0 = ot*32, k0 = kt*32;

    int tx = threadIdx.x & 31;
    int ty = threadIdx.x >> 5;
    #pragma unroll
    for (int s = 0; s < 4; s++) {
        int oy = ty + s*8;
        tile[tx][oy] = src[(size_t)(o0+oy)*K + k0 + tx];
    }
    __syncthreads();

    int oL  = threadIdx.x & 31;
    int k2b = threadIdx.x >> 5;
    #pragma unroll
    for (int s = 0; s < 2; s++) {
        int k2L = k2b + s*8;     // 0..15
        dst[(size_t)(k0/2 + k2L)*O + o0 + oL] =
            make_float2(tile[2*k2L][oL], tile[2*k2L+1][oL]);
    }
}

// ---------------------------------------------------------------------------
// K1 body: fused patch-conv + MLP + distances (R13 champion, byte-frozen).
// ---------------------------------------------------------------------------
template<int PTN>
__device__ __forceinline__ void mlp_body(
    int gp0, int tid, float* sA, float* sB, float* sC,
    const float* __restrict__ x,
    const float* __restrict__ bf, const float* __restrict__ b1,
    const float* __restrict__ b2, const float* __restrict__ b3,
    const float* __restrict__ b4, const float* __restrict__ prot)
{
    // ---- load PTN patches of input (3x16x16 each) into sA
    for (int e = tid; e < PTN*768; e += 256) {
        int pt = e / 768, k = e - pt*768;
        int c = k >> 8, r = (k >> 4) & 15, col = k & 15;
        int gp = gp0 + pt;
        int b = gp / NP, hw = gp - b*NP;
        int py = hw / HP, px = hw - py*HP;
        sA[e] = x[((b*3 + c)*224 + py*16 + r)*224 + px*16 + col];
    }
    __syncthreads();

    // ---- stage 0: 512 outputs (2/thread), K=768 : sA -> sB
    {
        float acc0[PTN], acc1[PTN];
        #pragma unroll
        for (int pt = 0; pt < PTN; pt++) { acc0[pt] = 0.f; acc1[pt] = 0.f; }
        #pragma unroll 2
        for (int k = 0; k < 768; k += 4) {
            float2 wa0 = g_Wft2[(k>>1)*512 + tid];
            float2 wa1 = g_Wft2[((k>>1)+1)*512 + tid];
            float2 wb0 = g_Wft2[(k>>1)*512 + tid + 256];
            float2 wb1 = g_Wft2[((k>>1)+1)*512 + tid + 256];
            #pragma unroll
            for (int pt = 0; pt < PTN; pt++) {
                float4 a = *(const float4*)&sA[pt*768 + k];
                acc0[pt] = fmaf(wa0.x, a.x, acc0[pt]);
                acc0[pt] = fmaf(wa0.y, a.y, acc0[pt]);
                acc0[pt] = fmaf(wa1.x, a.z, acc0[pt]);
                acc0[pt] = fmaf(wa1.y, a.w, acc0[pt]);
                acc1[pt] = fmaf(wb0.x, a.x, acc1[pt]);
                acc1[pt] = fmaf(wb0.y, a.y, acc1[pt]);
                acc1[pt] = fmaf(wb1.x, a.z, acc1[pt]);
                acc1[pt] = fmaf(wb1.y, a.w, acc1[pt]);
            }
        }
        float bb0 = bf[tid], bb1 = bf[tid + 256];
        #pragma unroll
        for (int pt = 0; pt < PTN; pt++) {
            sB[pt*512 + tid]       = fmaxf(acc0[pt] + bb0, 0.f);
            sB[pt*512 + tid + 256] = fmaxf(acc1[pt] + bb1, 0.f);
        }
    }
    __syncthreads();

    // ---- stage 1: 256 outputs, K=512 : sB -> sC
    {
        float acc[PTN];
        #pragma unroll
        for (int pt = 0; pt < PTN; pt++) acc[pt] = 0.f;
        #pragma unroll 2
        for (int k = 0; k < 512; k += 4) {
            float2 w0 = g_W1t2[(k>>1)*256 + tid];
            float2 w1 = g_W1t2[((k>>1)+1)*256 + tid];
            #pragma unroll
            for (int pt = 0; pt < PTN; pt++) {
                float4 a = *(const float4*)&sB[pt*512 + k];
                acc[pt] = fmaf(w0.x, a.x, acc[pt]);
                acc[pt] = fmaf(w0.y, a.y, acc[pt]);
                acc[pt] = fmaf(w1.x, a.z, acc[pt]);
                acc[pt] = fmaf(w1.y, a.w, acc[pt]);
            }
        }
        float bb = b1[tid];
        #pragma unroll
        for (int pt = 0; pt < PTN; pt++)
            sC[pt*256 + tid] = fmaxf(acc[pt] + bb, 0.f);
    }
    __syncthreads();

    // ---- stage 2: 256 outputs, K=256 : sC -> sA (reuse)
    {
        float acc[PTN];
        #pragma unroll
        for (int pt = 0; pt < PTN; pt++) acc[pt] = 0.f;
        #pragma unroll 2
        for (int k = 0; k < 256; k += 4) {
            float2 w0 = g_W2t2[(k>>1)*256 + tid];
            float2 w1 = g_W2t2[((k>>1)+1)*256 + tid];
            #pragma unroll
            for (int pt = 0; pt < PTN; pt++) {
                float4 a = *(const float4*)&sC[pt*256 + k];
                acc[pt] = fmaf(w0.x, a.x, acc[pt]);
                acc[pt] = fmaf(w0.y, a.y, acc[pt]);
                acc[pt] = fmaf(w1.x, a.z, acc[pt]);
                acc[pt] = fmaf(w1.y, a.w, acc[pt]);
            }
        }
        float bb = b2[tid];
        #pragma unroll
        for (int pt = 0; pt < PTN; pt++)
            sA[pt*256 + tid] = fmaxf(acc[pt] + bb, 0.f);
    }
    __syncthreads();

    // ---- stage 3: 128 outputs, K=256 : sA -> sB (thread: 1 out x <=6 patches)
    {
        const int o = tid & 127;
        const int half = tid >> 7;
        float acc[6] = {0.f, 0.f, 0.f, 0.f, 0.f, 0.f};
        #pragma unroll 2
        for (int k = 0; k < 256; k += 4) {
            float2 w0 = g_W3t2[(k>>1)*128 + o];
            float2 w1 = g_W3t2[((k>>1)+1)*128 + o];
            #pragma unroll
            for (int j = 0; j < 6; j++) {
                int pt = half*6 + j;
                if (pt < PTN) {
                    float4 a = *(const float4*)&sA[pt*256 + k];
                    acc[j] = fmaf(w0.x, a.x, acc[j]);
                    acc[j] = fmaf(w0.y, a.y, acc[j]);
                    acc[j] = fmaf(w1.x, a.z, acc[j]);
                    acc[j] = fmaf(w1.y, a.w, acc[j]);
                }
            }
        }
        float bb = b3[o];
        #pragma unroll
        for (int j = 0; j < 6; j++) {
            int pt = half*6 + j;
            if (pt < PTN)
                sB[pt*128 + o] = fmaxf(acc[j] + bb, 0.f);
        }
    }
    __syncthreads();

    // ---- stage 4: 128 outputs, K=128, sigmoid : sB -> sC
    {
        const int o = tid & 127;
        const int half = tid >> 7;
        float acc[6] = {0.f, 0.f, 0.f, 0.f, 0.f, 0.f};
        #pragma unroll 2
        for (int k = 0; k < 128; k += 4) {
            float2 w0 = g_W4t2[(k>>1)*128 + o];
            float2 w1 = g_W4t2[((k>>1)+1)*128 + o];
            #pragma unroll
            for (int j = 0; j < 6; j++) {
                int pt = half*6 + j;
                if (pt < PTN) {
                    float4 a = *(const float4*)&sB[pt*128 + k];
                    acc[j] = fmaf(w0.x, a.x, acc[j]);
                    acc[j] = fmaf(w0.y, a.y, acc[j]);
                    acc[j] = fmaf(w1.x, a.z, acc[j]);
                    acc[j] = fmaf(w1.y, a.w, acc[j]);
                }
            }
        }
        float bb = b4[o];
        #pragma unroll
        for (int j = 0; j < 6; j++) {
            int pt = half*6 + j;
            if (pt < PTN) {
                float z = acc[j] + bb;
                sC[pt*128 + o] = 1.0f / (1.0f + expf(-z));
            }
        }
    }
    __syncthreads();

    // ---- prototype distances + activation: 60 protos x PTN patches
    for (int q = tid; q < PROTO*PTN; q += 256) {
        int p = q / PTN, pt = q - p*PTN;
        const float* pr = prot + p*128;
        const float* hh = sC + pt*128;
        float acc = 0.f;
        #pragma unroll 8
        for (int k = 0; k < 128; k += 4) {
            float4 h4 = *(const float4*)&hh[k];
            float4 p4 = *(const float4*)&pr[k];
            float d0 = h4.x - p4.x, d1 = h4.y - p4.y;
            float d2 = h4.z - p4.z, d3 = h4.w - p4.w;
            acc = fmaf(d0, d0, acc); acc = fmaf(d1, d1, acc);
            acc = fmaf(d2, d2, acc); acc = fmaf(d3, d3, acc);
        }
        float d = sqrtf(acc);
        float a = logf((d + 1.0f) / (d + EPSV));
        int gp = gp0 + pt;
        int b = gp / NP, hw = gp - b*NP;
        int idx = (b*PROTO + p)*NP + hw;
        g_dist[idx] = d;
        g_act[idx]  = a;
    }
}

__global__ __launch_bounds__(256, 2) void k_mlp(
    const float* __restrict__ x,
    const float* __restrict__ bf, const float* __restrict__ b1,
    const float* __restrict__ b2, const float* __restrict__ b3,
    const float* __restrict__ b4, const float* __restrict__ prot)
{
    extern __shared__ float sm[];
    float* sA = sm;                 // PTMAX*768; reused as h2
    float* sB = sm + PTMAX*768;     // PTMAX*512; reused as h3
    float* sC = sB + PTMAX*512;     // PTMAX*256; h1, then h4

    const int tid = threadIdx.x;
    const int bid = blockIdx.x;

    // 176 blocks of 11 patches + 120 blocks of 10 patches = 3136
    if (bid < 176) {
        mlp_body<11>(bid*11, tid, sA, sB, sC, x, bf, b1, b2, b3, b4, prot);
    } else {
        mlp_body<10>(1936 + (bid-176)*10, tid, sA, sB, sC, x, bf, b1, b2, b3, b4, prot);
    }
}

// ---------------------------------------------------------------------------
// K2: per-batch top-k + logits (proven). One block per image, 16 warps.
// ---------------------------------------------------------------------------
__global__ __launch_bounds__(512) void k_tkl(
    const int* __restrict__ kptr, const float* __restrict__ lastW,
    float* __restrict__ out_log, float* __restrict__ out_mind)
{
    __shared__ float sp[PROTO];
    const int b    = blockIdx.x;
    const int warp = threadIdx.x >> 5;
    const int lane = threadIdx.x & 31;
    const int k    = *kptr;

    for (int p = warp; p < PROTO; p += 16) {
        const float* dp = g_dist + (b*PROTO + p)*NP;
        float v[7];
        #pragma unroll
        for (int j = 0; j < 7; j++) {
            int i = lane + 32*j;
            v[j] = (i < NP) ? dp[i] : 1e30f;
        }
        float sd = 0.f, sa = 0.f;
        for (int it = 0; it < k; it++) {
            float m = v[0]; int mj = 0;
            #pragma unroll
            for (int j = 1; j < 7; j++) if (v[j] < m) { m = v[j]; mj = j; }
            float bm = m; int bidx = (mj << 5) | lane;
            #pragma unroll
            for (int off = 16; off; off >>= 1) {
                float om = __shfl_xor_sync(0xffffffffu, bm, off);
                int   oi = __shfl_xor_sync(0xffffffffu, bidx, off);
                if (om < bm || (om == bm && oi < bidx)) { bm = om; bidx = oi; }
            }
            sd += bm;
            sa += logf((bm + 1.0f) / (bm + EPSV));
            if (lane == (bidx & 31)) v[bidx >> 5] = 1e30f;
        }
        if (lane == 0) {
            out_mind[b*PROTO + p] = sd / (float)k;
            sp[p] = sa / (float)k;
        }
    }
    __syncthreads();
    int t = threadIdx.x;
    if (t < 3) {
        float s = 0.f;
        #pragma unroll
        for (int p = 0; p < PROTO; p++)
            s += sp[p] * lastW[t*PROTO + p];
        out_log[b*3 + t] = s;
    }
}

// ---------------------------------------------------------------------------
// K3: 16x upsample. 2 feature-rows per block, one contiguous 28672B
// cp.async.bulk store. At the LTS/DRAM-write ceiling — frozen.
// ---------------------------------------------------------------------------
__global__ __launch_bounds__(128) void k_ups(float* __restrict__ out_up)
{
    __shared__ alignas(128) float buf[7168];   // 32 rows x 224 = 28672 B
    __shared__ float sv[28];
    const int bid = blockIdx.x;                // 16*60*7 = 6720
    const int bp  = bid / 7;
    const int py0 = (bid - bp*7) * 2;
    const int tid = threadIdx.x;

    if (tid < 28) sv[tid] = g_act[bp*NP + py0*HP + tid];  // 2 rows of 14
    __syncthreads();

    #pragma unroll
    for (int it = 0; it < 14; it++) {
        int idx = tid + it*128;        // float4 index 0..1791
        int row = idx / 56;            // 0..31 output rows
        int xq  = idx - row*56;
        float v = sv[(row >> 4)*14 + (xq >> 2)];
        ((float4*)buf)[idx] = make_float4(v, v, v, v);
    }
    __syncthreads();

    if (tid == 0) {
        float* dst = out_up + (size_t)bp*50176 + (size_t)py0*3584;
        unsigned saddr = (unsigned)__cvta_generic_to_shared(buf);
        asm volatile("fence.proxy.async.shared::cta;" ::: "memory");
        asm volatile("cp.async.bulk.global.shared::cta.bulk_group [%0], [%1], %2;"
                     :: "l"(dst), "r"(saddr), "r"(28672) : "memory");
        asm volatile("cp.async.bulk.commit_group;" ::: "memory");
        asm volatile("cp.async.bulk.wait_group 0;" ::: "memory");
    }
}

// ---------------------------------------------------------------------------
extern "C" void kernel_launch(void* const* d_in, const int* in_sizes, int n_in,
                              void* d_out, int out_size)
{
    const float* x    = (const float*)d_in[0];
    // d_in[1] = mascaras (unused by reference)
    const float* Wf   = (const float*)d_in[2];
    const float* bf   = (const float*)d_in[3];
    const float* W1   = (const float*)d_in[4];
    const float* b1   = (const float*)d_in[5];
    const float* W2   = (const float*)d_in[6];
    const float* b2   = (const float*)d_in[7];
    const float* W3   = (const float*)d_in[8];
    const float* b3   = (const float*)d_in[9];
    const float* W4   = (const float*)d_in[10];
    const float* b4   = (const float*)d_in[11];
    const float* prot = (const float*)d_in[12];
    const float* lastW= (const float*)d_in[13];
    const int*   kptr = (const int*)d_in[14];
    float* out = (float*)d_out;

    // One-time host-side handles (no device memory; identical device work
    // every call). Created on the first (uncaptured) correctness call.
    static cudaStream_t s_side = nullptr;
    static cudaEvent_t  s_fork = nullptr, s_join = nullptr;
    if (s_side == nullptr) {
        cudaStreamCreateWithFlags(&s_side, cudaStreamNonBlocking);
        cudaEventCreateWithFlags(&s_fork, cudaEventDisableTiming);
        cudaEventCreateWithFlags(&s_join, cudaEventDisableTiming);
    }

    const int SMEM = (PTMAX*768 + PTMAX*512 + PTMAX*256) * 4;   // 67584 bytes
    cudaFuncSetAttribute(k_mlp, cudaFuncAttributeMaxDynamicSharedMemorySize, SMEM);

    // output packing: logits[48] | min_distances[960] | upsampled[16*60*224*224]
    k_tr <<<624, 256>>>(Wf, W1, W2, W3, W4);
    k_mlp<<<NBLK, 256, SMEM>>>(x, bf, b1, b2, b3, b4, prot);

    // fork: k_ups on the side stream, k_tkl on the main stream, then join
    cudaEventRecord(s_fork, 0);
    cudaStreamWaitEvent(s_side, s_fork, 0);
    k_ups<<<6720, 128, 0, s_side>>>(out + 48 + NB*PROTO);
    cudaEventRecord(s_join, s_side);

    k_tkl<<<NB, 512>>>(kptr, lastW, out, out + 48);
    cudaStreamWaitEvent(0, s_join, 0);
}